// round 1
// baseline (speedup 1.0000x reference)
#include <cuda_runtime.h>
#include <math_constants.h>

#define NNODES 65536
#define NEDGES 1048576
#define NGRAPH 64
#define NPER   1024
#define FEAT   64
#define HID    128
#define TOPK   10

// ---------------- device scratch (no allocations allowed) ----------------
__device__ int   g_deg[NNODES];
__device__ float g_dinv[NNODES];
__device__ int   g_off[NNODES];
__device__ int   g_cursor[NNODES];
__device__ int   g_bsum[256];
__device__ int   g_csrsrc[NEDGES];
__device__ float g_csrnrm[NEDGES];
__device__ float g_c[NNODES];
__device__ float g_T0[NNODES * HID];
__device__ float g_T1[NNODES * HID];
__device__ float g_T2[NNODES * HID];
__device__ float g_mp[NGRAPH * HID];
__device__ float g_gW[NGRAPH * HID];
__device__ float g_z[NNODES];
__device__ float g_logit[NNODES];

// ---------------- CSR construction ----------------
__global__ void k_zero_deg() {
    int i = blockIdx.x * 256 + threadIdx.x;
    if (i < NNODES) g_deg[i] = 0;
}

__global__ void k_hist(const int* __restrict__ edst) {
    int e = blockIdx.x * 256 + threadIdx.x;
    if (e < NEDGES) atomicAdd(&g_deg[edst[e]], 1);
}

__global__ void k_dinv() {
    int i = blockIdx.x * 256 + threadIdx.x;
    if (i < NNODES) g_dinv[i] = rsqrtf((float)(g_deg[i] + 1));
}

__global__ void k_scan1() {
    __shared__ int s[256];
    int t = threadIdx.x;
    int i = blockIdx.x * 256 + t;
    int v = g_deg[i];
    s[t] = v;
    __syncthreads();
    for (int off = 1; off < 256; off <<= 1) {
        int x = s[t];
        if (t >= off) x += s[t - off];
        __syncthreads();
        s[t] = x;
        __syncthreads();
    }
    g_off[i] = s[t] - v;
    if (t == 255) g_bsum[blockIdx.x] = s[t];
}

__global__ void k_scan2() {
    __shared__ int s[256];
    int t = threadIdx.x;
    int v = g_bsum[t];
    s[t] = v;
    __syncthreads();
    for (int off = 1; off < 256; off <<= 1) {
        int x = s[t];
        if (t >= off) x += s[t - off];
        __syncthreads();
        s[t] = x;
        __syncthreads();
    }
    g_bsum[t] = s[t] - v;   // exclusive
}

__global__ void k_scan3() {
    int i = blockIdx.x * 256 + threadIdx.x;
    int o = g_off[i] + g_bsum[blockIdx.x];
    g_off[i] = o;
    g_cursor[i] = o;
}

__global__ void k_fill(const int* __restrict__ esrc, const int* __restrict__ edst) {
    int e = blockIdx.x * 256 + threadIdx.x;
    if (e >= NEDGES) return;
    int s = esrc[e], d = edst[e];
    float nr = g_dinv[s] * g_dinv[d];
    int slot = atomicAdd(&g_cursor[d], 1);
    g_csrsrc[slot] = s;
    g_csrnrm[slot] = nr;
}

__global__ void k_cvec() {
    int i = blockIdx.x * 256 + threadIdx.x;
    if (i >= NNODES) return;
    float dv = g_dinv[i];
    float sum = dv * dv;
    int jb = g_off[i], cnt = g_deg[i];
    for (int j = 0; j < cnt; j++) sum += g_csrnrm[jb + j];
    g_c[i] = sum;
}

// ---------------- sparse aggregations (warp per node, gather) ----------------
__global__ void k_agg64(const float* __restrict__ X, float* __restrict__ Y) {
    int node = blockIdx.x * 8 + (threadIdx.x >> 5);
    int lane = threadIdx.x & 31;
    const float2* xs = (const float2*)X;
    float dv = g_dinv[node];
    float2 xv = xs[node * 32 + lane];
    float2 acc;
    acc.x = dv * dv * xv.x;
    acc.y = dv * dv * xv.y;
    int jb = g_off[node], je = jb + g_deg[node];
    #pragma unroll 2
    for (int j = jb; j < je; j++) {
        int s = g_csrsrc[j];
        float nr = g_csrnrm[j];
        float2 v = xs[s * 32 + lane];
        acc.x += nr * v.x;
        acc.y += nr * v.y;
    }
    ((float2*)Y)[node * 32 + lane] = acc;
}

__global__ void k_agg128(const float* __restrict__ X, float* __restrict__ Y) {
    int node = blockIdx.x * 8 + (threadIdx.x >> 5);
    int lane = threadIdx.x & 31;
    const float4* xs = (const float4*)X;
    float dv = g_dinv[node];
    float4 xv = xs[node * 32 + lane];
    float4 acc;
    float sl = dv * dv;
    acc.x = sl * xv.x; acc.y = sl * xv.y; acc.z = sl * xv.z; acc.w = sl * xv.w;
    int jb = g_off[node], je = jb + g_deg[node];
    #pragma unroll 2
    for (int j = jb; j < je; j++) {
        int s = g_csrsrc[j];
        float nr = g_csrnrm[j];
        float4 v = xs[s * 32 + lane];
        acc.x += nr * v.x; acc.y += nr * v.y; acc.z += nr * v.z; acc.w += nr * v.w;
    }
    ((float4*)Y)[node * 32 + lane] = acc;
}

// ---------------- dense GEMM: Y[64rows/blk,128] = op(A@W + b (+ c*gW)) ----------------
template <int IN, bool RELU, bool GLOB>
__global__ void k_gemm(const float* __restrict__ A, const float* __restrict__ W,
                       const float* __restrict__ bias, float* __restrict__ Y) {
    extern __shared__ float sm[];
    float* sW = sm;             // IN x 128
    float* sA = sm + IN * 128;  // 64 x IN
    const int tid = threadIdx.x;
    for (int i = tid; i < IN * 128; i += 256) sW[i] = W[i];
    const int rbase = blockIdx.x * 64;
    for (int i = tid; i < 64 * IN; i += 256) sA[i] = A[(size_t)rbase * IN + i];
    __syncthreads();
    const int lane = tid & 31, wid = tid >> 5;
    float4 bv = *(const float4*)&bias[lane * 4];
    #pragma unroll
    for (int gidx = 0; gidx < 2; gidx++) {
        int r0 = wid * 8 + gidx * 4;
        float4 a0 = {0,0,0,0}, a1 = {0,0,0,0}, a2 = {0,0,0,0}, a3 = {0,0,0,0};
        const float* p0 = &sA[(r0 + 0) * IN];
        const float* p1 = &sA[(r0 + 1) * IN];
        const float* p2 = &sA[(r0 + 2) * IN];
        const float* p3 = &sA[(r0 + 3) * IN];
        #pragma unroll 8
        for (int k = 0; k < IN; k++) {
            float4 w = *(const float4*)&sW[k * 128 + lane * 4];
            float x0 = p0[k], x1 = p1[k], x2 = p2[k], x3 = p3[k];
            a0.x += x0 * w.x; a0.y += x0 * w.y; a0.z += x0 * w.z; a0.w += x0 * w.w;
            a1.x += x1 * w.x; a1.y += x1 * w.y; a1.z += x1 * w.z; a1.w += x1 * w.w;
            a2.x += x2 * w.x; a2.y += x2 * w.y; a2.z += x2 * w.z; a2.w += x2 * w.w;
            a3.x += x3 * w.x; a3.y += x3 * w.y; a3.z += x3 * w.z; a3.w += x3 * w.w;
        }
        float4 accs[4] = {a0, a1, a2, a3};
        #pragma unroll
        for (int rr = 0; rr < 4; rr++) {
            int row = rbase + r0 + rr;
            float4 acc = accs[rr];
            acc.x += bv.x; acc.y += bv.y; acc.z += bv.z; acc.w += bv.w;
            if (GLOB) {
                float cc = g_c[row];
                float4 gv = *(const float4*)&g_gW[(row >> 10) * HID + lane * 4];
                acc.x += cc * gv.x; acc.y += cc * gv.y; acc.z += cc * gv.z; acc.w += cc * gv.w;
            }
            if (RELU) {
                acc.x = fmaxf(acc.x, 0.f); acc.y = fmaxf(acc.y, 0.f);
                acc.z = fmaxf(acc.z, 0.f); acc.w = fmaxf(acc.w, 0.f);
            }
            *(float4*)&Y[(size_t)row * 128 + lane * 4] = acc;
        }
    }
}

// ---------------- max pool + small matmuls for global path ----------------
__global__ void k_maxpool(const float* __restrict__ H) {
    int g = blockIdx.x, f = threadIdx.x;
    const float* p = H + (size_t)g * NPER * HID + f;
    float m = -CUDART_INF_F;
    for (int i = 0; i < NPER; i++) m = fmaxf(m, p[(size_t)i * HID]);
    g_mp[g * HID + f] = m;
}

// glob = mp @ Wf + bf ; gW = glob @ W2[128:256,:]
__global__ void k_globs(const float* __restrict__ Wf, const float* __restrict__ bf,
                        const float* __restrict__ W2) {
    __shared__ float s1[HID];
    __shared__ float s2[HID];
    int g = blockIdx.x, t = threadIdx.x;
    s1[t] = g_mp[g * HID + t];
    __syncthreads();
    float acc = bf[t];
    for (int k = 0; k < HID; k++) acc += s1[k] * Wf[k * HID + t];
    s2[t] = acc;
    __syncthreads();
    float a2 = 0.f;
    for (int k = 0; k < HID; k++) a2 += s2[k] * W2[(HID + k) * HID + t];
    g_gW[g * HID + t] = a2;
}

// ---------------- final projection + scalar aggregation ----------------
__global__ void k_z(const float* __restrict__ H, const float* __restrict__ W3) {
    int node = blockIdx.x * 8 + (threadIdx.x >> 5);
    int lane = threadIdx.x & 31;
    float4 h = ((const float4*)H)[node * 32 + lane];
    float4 w = ((const float4*)W3)[lane];
    float d = h.x * w.x + h.y * w.y + h.z * w.z + h.w * w.w;
    #pragma unroll
    for (int o = 16; o; o >>= 1) d += __shfl_xor_sync(0xffffffffu, d, o);
    if (lane == 0) g_z[node] = d;
}

__global__ void k_logit(const float* __restrict__ b3) {
    int node = blockIdx.x * 8 + (threadIdx.x >> 5);
    int lane = threadIdx.x & 31;
    int jb = g_off[node], je = jb + g_deg[node];
    float part = 0.f;
    for (int j = jb + lane; j < je; j += 32)
        part += g_csrnrm[j] * g_z[g_csrsrc[j]];
    #pragma unroll
    for (int o = 16; o; o >>= 1) part += __shfl_xor_sync(0xffffffffu, part, o);
    if (lane == 0) {
        float dv = g_dinv[node];
        g_logit[node] = part + dv * dv * g_z[node] + b3[0];
    }
}

// ---------------- per-graph top-K threshold + mask ----------------
__global__ void k_topk(float* __restrict__ out) {
    __shared__ float v[NPER];
    __shared__ float wmax[8];
    __shared__ float sth;
    __shared__ int sidx;
    int g = blockIdx.x, t = threadIdx.x;
    int lane = t & 31, warp = t >> 5;
    for (int i = t; i < NPER; i += 256) v[i] = g_logit[g * NPER + i];
    __syncthreads();
    for (int it = 0; it < TOPK; it++) {
        float m = -CUDART_INF_F;
        for (int i = t; i < NPER; i += 256) m = fmaxf(m, v[i]);
        #pragma unroll
        for (int o = 16; o; o >>= 1) m = fmaxf(m, __shfl_xor_sync(0xffffffffu, m, o));
        if (lane == 0) wmax[warp] = m;
        __syncthreads();
        if (t == 0) {
            float mm = wmax[0];
            #pragma unroll
            for (int w = 1; w < 8; w++) mm = fmaxf(mm, wmax[w]);
            sth = mm;
            sidx = 0x7fffffff;
        }
        __syncthreads();
        float mm = sth;
        for (int i = t; i < NPER; i += 256)
            if (v[i] == mm) atomicMin(&sidx, i);
        __syncthreads();
        if (t == 0) v[sidx] = -CUDART_INF_F;
        __syncthreads();
    }
    float th = sth;   // 10th largest (ties counted, matches jnp top_k semantics)
    for (int i = t; i < NPER; i += 256)
        out[g * NPER + i] = (g_logit[g * NPER + i] >= th) ? 1.0f : 0.0f;
}

// ---------------- host launcher ----------------
extern "C" void kernel_launch(void* const* d_in, const int* in_sizes, int n_in,
                              void* d_out, int out_size) {
    const float* x    = (const float*)d_in[0];
    const int*   esrc = (const int*)d_in[1];
    const int*   edst = (const int*)d_in[2];
    // d_in[3] = uniforms (unused in eval path)
    const float* W0 = (const float*)d_in[4];
    const float* b0 = (const float*)d_in[5];
    const float* W1 = (const float*)d_in[6];
    const float* b1 = (const float*)d_in[7];
    const float* Wf = (const float*)d_in[8];
    const float* bf = (const float*)d_in[9];
    const float* W2 = (const float*)d_in[10];
    const float* b2 = (const float*)d_in[11];
    const float* W3 = (const float*)d_in[12];
    const float* b3 = (const float*)d_in[13];
    float* out = (float*)d_out;

    float *T0, *T1, *T2;
    cudaGetSymbolAddress((void**)&T0, g_T0);
    cudaGetSymbolAddress((void**)&T1, g_T1);
    cudaGetSymbolAddress((void**)&T2, g_T2);

    const int SMEM64  = (64 * 128 + 64 * 64) * 4;    // 48 KB
    const int SMEM128 = (128 * 128 + 64 * 128) * 4;  // 96 KB
    cudaFuncSetAttribute(k_gemm<64, true, false>,  cudaFuncAttributeMaxDynamicSharedMemorySize, SMEM64);
    cudaFuncSetAttribute(k_gemm<128, true, false>, cudaFuncAttributeMaxDynamicSharedMemorySize, SMEM128);
    cudaFuncSetAttribute(k_gemm<128, true, true>,  cudaFuncAttributeMaxDynamicSharedMemorySize, SMEM128);

    // --- CSR + norms ---
    k_zero_deg<<<NNODES / 256, 256>>>();
    k_hist<<<NEDGES / 256, 256>>>(edst);
    k_dinv<<<NNODES / 256, 256>>>();
    k_scan1<<<256, 256>>>();
    k_scan2<<<1, 256>>>();
    k_scan3<<<256, 256>>>();
    k_fill<<<NEDGES / 256, 256>>>(esrc, edst);
    k_cvec<<<NNODES / 256, 256>>>();

    // --- conv0: h0 = relu(agg(x) @ W0 + b0) ---
    k_agg64<<<NNODES / 8, 256>>>(x, T2);
    k_gemm<64, true, false><<<NNODES / 64, 256, SMEM64>>>(T2, W0, b0, T0);

    // --- global path: maxpool(h0) @ Wf + bf, then @ W2_bottom ---
    k_maxpool<<<NGRAPH, HID>>>(T0);
    k_globs<<<NGRAPH, HID>>>(Wf, bf, W2);

    // --- conv1 (applied twice with same weights) ---
    k_agg128<<<NNODES / 8, 256>>>(T0, T1);
    k_gemm<128, true, false><<<NNODES / 64, 256, SMEM128>>>(T1, W1, b1, T2);
    k_agg128<<<NNODES / 8, 256>>>(T2, T1);
    k_gemm<128, true, false><<<NNODES / 64, 256, SMEM128>>>(T1, W1, b1, T0);

    // --- conv2 on concat: relu(agg(h) @ W2_top + c_n * gW + b2) ---
    k_agg128<<<NNODES / 8, 256>>>(T0, T1);
    k_gemm<128, true, true><<<NNODES / 64, 256, SMEM128>>>(T1, W2, b2, T2);

    // --- conv3 (out=1): z = h @ W3, logit = agg(z) + b3 ---
    k_z<<<NNODES / 8, 256>>>(T2, W3);
    k_logit<<<NNODES / 8, 256>>>(b3);

    // --- per-graph top-10 threshold mask ---
    k_topk<<<NGRAPH, 256>>>(out);
}

// round 3
// speedup vs baseline: 1.0550x; 1.0550x over previous
#include <cuda_runtime.h>
#include <math_constants.h>
#include <cstdint>

#define NNODES 65536
#define NEDGES 1048576
#define NGRAPH 64
#define NPER   1024
#define FEAT   64
#define HID    128
#define TOPK   10

// ---------------- device scratch (no allocations allowed) ----------------
__device__ int   g_deg[NNODES];
__device__ float g_dinv[NNODES];
__device__ int   g_off[NNODES];
__device__ int   g_cursor[NNODES];
__device__ int   g_bsum[256];
__device__ int   g_csrsrc[NEDGES];
__device__ float g_csrnrm[NEDGES];
__device__ float g_c[NNODES];
__device__ float g_T0[NNODES * HID];
__device__ float g_T1[NNODES * HID];
__device__ float g_T2[NNODES * HID];
__device__ float g_mpp[NGRAPH * 8 * HID];
__device__ float g_mp[NGRAPH * HID];
__device__ float g_gW[NGRAPH * HID];
__device__ float g_z[NNODES];
__device__ float g_logit[NNODES];

// ---------------- tf32 helpers ----------------
__device__ __forceinline__ void split_tf32(float a, uint32_t& hi, uint32_t& lo) {
    asm("cvt.rna.tf32.f32 %0, %1;" : "=r"(hi) : "f"(a));
    float r = a - __uint_as_float(hi);
    asm("cvt.rna.tf32.f32 %0, %1;" : "=r"(lo) : "f"(r));
}

__device__ __forceinline__ void mma_tf32(float4& d, const uint32_t a[4], const uint32_t b[2]) {
    asm volatile(
        "mma.sync.aligned.m16n8k8.row.col.f32.tf32.tf32.f32 "
        "{%0,%1,%2,%3}, {%4,%5,%6,%7}, {%8,%9}, {%0,%1,%2,%3};"
        : "+f"(d.x), "+f"(d.y), "+f"(d.z), "+f"(d.w)
        : "r"(a[0]), "r"(a[1]), "r"(a[2]), "r"(a[3]), "r"(b[0]), "r"(b[1]));
}

// ---------------- CSR construction ----------------
__global__ void k_zero_deg() {
    int i = blockIdx.x * 256 + threadIdx.x;
    if (i < NNODES) g_deg[i] = 0;
}

__global__ void k_hist(const int* __restrict__ edst) {
    int e = blockIdx.x * 256 + threadIdx.x;
    if (e < NEDGES) atomicAdd(&g_deg[edst[e]], 1);
}

__global__ void k_dinv() {
    int i = blockIdx.x * 256 + threadIdx.x;
    if (i < NNODES) g_dinv[i] = rsqrtf((float)(g_deg[i] + 1));
}

__global__ void k_scan1() {
    __shared__ int s[256];
    int t = threadIdx.x;
    int i = blockIdx.x * 256 + t;
    int v = g_deg[i];
    s[t] = v;
    __syncthreads();
    for (int off = 1; off < 256; off <<= 1) {
        int x = s[t];
        if (t >= off) x += s[t - off];
        __syncthreads();
        s[t] = x;
        __syncthreads();
    }
    g_off[i] = s[t] - v;
    if (t == 255) g_bsum[blockIdx.x] = s[t];
}

__global__ void k_scan2() {
    __shared__ int s[256];
    int t = threadIdx.x;
    int v = g_bsum[t];
    s[t] = v;
    __syncthreads();
    for (int off = 1; off < 256; off <<= 1) {
        int x = s[t];
        if (t >= off) x += s[t - off];
        __syncthreads();
        s[t] = x;
        __syncthreads();
    }
    g_bsum[t] = s[t] - v;   // exclusive
}

__global__ void k_scan3() {
    int i = blockIdx.x * 256 + threadIdx.x;
    int o = g_off[i] + g_bsum[blockIdx.x];
    g_off[i] = o;
    g_cursor[i] = o;
}

__global__ void k_fill(const int* __restrict__ esrc, const int* __restrict__ edst) {
    int e = blockIdx.x * 256 + threadIdx.x;
    if (e >= NEDGES) return;
    int s = esrc[e], d = edst[e];
    float nr = g_dinv[s] * g_dinv[d];
    int slot = atomicAdd(&g_cursor[d], 1);
    g_csrsrc[slot] = s;
    g_csrnrm[slot] = nr;
}

__global__ void k_cvec() {
    int i = blockIdx.x * 256 + threadIdx.x;
    if (i >= NNODES) return;
    float dv = g_dinv[i];
    float sum = dv * dv;
    int jb = g_off[i], cnt = g_deg[i];
    for (int j = 0; j < cnt; j++) sum += g_csrnrm[jb + j];
    g_c[i] = sum;
}

// ---------------- sparse aggregations (warp per node, gather) ----------------
__global__ void k_agg64(const float* __restrict__ X, float* __restrict__ Y) {
    int node = blockIdx.x * 8 + (threadIdx.x >> 5);
    int lane = threadIdx.x & 31;
    const float2* xs = (const float2*)X;
    float dv = g_dinv[node];
    float2 xv = xs[node * 32 + lane];
    float2 acc;
    acc.x = dv * dv * xv.x;
    acc.y = dv * dv * xv.y;
    int jb = g_off[node], je = jb + g_deg[node];
    #pragma unroll 2
    for (int j = jb; j < je; j++) {
        int s = g_csrsrc[j];
        float nr = g_csrnrm[j];
        float2 v = xs[s * 32 + lane];
        acc.x += nr * v.x;
        acc.y += nr * v.y;
    }
    ((float2*)Y)[node * 32 + lane] = acc;
}

__global__ void k_agg128(const float* __restrict__ X, float* __restrict__ Y) {
    int node = blockIdx.x * 8 + (threadIdx.x >> 5);
    int lane = threadIdx.x & 31;
    const float4* xs = (const float4*)X;
    float dv = g_dinv[node];
    float4 xv = xs[node * 32 + lane];
    float4 acc;
    float sl = dv * dv;
    acc.x = sl * xv.x; acc.y = sl * xv.y; acc.z = sl * xv.z; acc.w = sl * xv.w;
    int jb = g_off[node], je = jb + g_deg[node];
    #pragma unroll 2
    for (int j = jb; j < je; j++) {
        int s = g_csrsrc[j];
        float nr = g_csrnrm[j];
        float4 v = xs[s * 32 + lane];
        acc.x += nr * v.x; acc.y += nr * v.y; acc.z += nr * v.z; acc.w += nr * v.w;
    }
    ((float4*)Y)[node * 32 + lane] = acc;
}

// ---------------- 3xTF32 mma.sync GEMM: Y[128 rows/blk, 128] ----------------
// smem: sA[128][K+4], sB[K][136] (both padded for conflict-free fragment LDS)
template <int K, bool RELU, bool GLOB>
__global__ __launch_bounds__(256) void k_mgemm(
    const float* __restrict__ A, const float* __restrict__ W,
    const float* __restrict__ bias, float* __restrict__ Y) {
    extern __shared__ float sm[];
    const int PA = K + 4;
    float* sA = sm;                 // 128 * PA
    float* sB = sm + 128 * PA;      // K * 136
    const int tid = threadIdx.x;
    const int rbase = blockIdx.x * 128;

    // stage A tile
    for (int i = tid; i < 128 * (K / 4); i += 256) {
        int row = i / (K / 4), c = i % (K / 4);
        float4 v = *(const float4*)&A[(size_t)(rbase + row) * K + c * 4];
        *(float4*)&sA[row * PA + c * 4] = v;
    }
    // stage W
    for (int i = tid; i < K * 32; i += 256) {
        int row = i / 32, c = i % 32;
        *(float4*)&sB[row * 136 + c * 4] = *(const float4*)&W[row * 128 + c * 4];
    }
    __syncthreads();

    const int lane = tid & 31, wid = tid >> 5;
    const int gp = lane >> 2, tg = lane & 3;
    const int m0 = (wid & 3) * 32, n0 = (wid >> 2) * 64;

    float4 acc[2][8];
    #pragma unroll
    for (int mf = 0; mf < 2; mf++)
        #pragma unroll
        for (int f = 0; f < 8; f++) acc[mf][f] = make_float4(0.f, 0.f, 0.f, 0.f);

    for (int ks = 0; ks < K / 8; ks++) {
        const int kc = ks * 8;
        uint32_t ah[2][4], al[2][4];
        #pragma unroll
        for (int mf = 0; mf < 2; mf++) {
            int r0 = m0 + mf * 16 + gp;
            float x0 = sA[r0 * PA + kc + tg];
            float x1 = sA[(r0 + 8) * PA + kc + tg];
            float x2 = sA[r0 * PA + kc + tg + 4];
            float x3 = sA[(r0 + 8) * PA + kc + tg + 4];
            split_tf32(x0, ah[mf][0], al[mf][0]);
            split_tf32(x1, ah[mf][1], al[mf][1]);
            split_tf32(x2, ah[mf][2], al[mf][2]);
            split_tf32(x3, ah[mf][3], al[mf][3]);
        }
        #pragma unroll
        for (int f = 0; f < 8; f++) {
            int n = n0 + f * 8 + gp;
            float y0 = sB[(kc + tg) * 136 + n];
            float y1 = sB[(kc + tg + 4) * 136 + n];
            uint32_t bh[2], bl[2];
            split_tf32(y0, bh[0], bl[0]);
            split_tf32(y1, bh[1], bl[1]);
            #pragma unroll
            for (int mf = 0; mf < 2; mf++) {
                mma_tf32(acc[mf][f], ah[mf], bh);
                mma_tf32(acc[mf][f], ah[mf], bl);
                mma_tf32(acc[mf][f], al[mf], bh);
            }
        }
    }

    // epilogue
    const float* gw = GLOB ? &g_gW[(rbase >> 10) * HID] : nullptr;
    #pragma unroll
    for (int mf = 0; mf < 2; mf++) {
        int r0 = rbase + m0 + mf * 16 + gp;
        int r1 = r0 + 8;
        float cc0 = GLOB ? g_c[r0] : 0.f;
        float cc1 = GLOB ? g_c[r1] : 0.f;
        #pragma unroll
        for (int f = 0; f < 8; f++) {
            int c = n0 + f * 8 + 2 * tg;
            float2 bv = *(const float2*)&bias[c];
            float4 a = acc[mf][f];
            float2 o0 = {a.x + bv.x, a.y + bv.y};
            float2 o1 = {a.z + bv.x, a.w + bv.y};
            if (GLOB) {
                float2 gv = *(const float2*)&gw[c];
                o0.x += cc0 * gv.x; o0.y += cc0 * gv.y;
                o1.x += cc1 * gv.x; o1.y += cc1 * gv.y;
            }
            if (RELU) {
                o0.x = fmaxf(o0.x, 0.f); o0.y = fmaxf(o0.y, 0.f);
                o1.x = fmaxf(o1.x, 0.f); o1.y = fmaxf(o1.y, 0.f);
            }
            *(float2*)&Y[(size_t)r0 * 128 + c] = o0;
            *(float2*)&Y[(size_t)r1 * 128 + c] = o1;
        }
    }
}

// ---------------- max pool (two stage) + small matmuls for global path ----------------
__global__ void k_maxpool1(const float* __restrict__ H) {
    int g = blockIdx.x >> 3, s = blockIdx.x & 7, f = threadIdx.x;
    const float* p = H + ((size_t)g * NPER + s * 128) * HID + f;
    float m = -CUDART_INF_F;
    for (int i = 0; i < 128; i++) m = fmaxf(m, p[(size_t)i * HID]);
    g_mpp[(g * 8 + s) * HID + f] = m;
}

__global__ void k_maxpool2() {
    int g = blockIdx.x, f = threadIdx.x;
    float m = -CUDART_INF_F;
    #pragma unroll
    for (int s = 0; s < 8; s++) m = fmaxf(m, g_mpp[(g * 8 + s) * HID + f]);
    g_mp[g * HID + f] = m;
}

// glob = mp @ Wf + bf ; gW = glob @ W2[128:256,:]
__global__ void k_globs(const float* __restrict__ Wf, const float* __restrict__ bf,
                        const float* __restrict__ W2) {
    __shared__ float s1[HID];
    __shared__ float s2[HID];
    int g = blockIdx.x, t = threadIdx.x;
    s1[t] = g_mp[g * HID + t];
    __syncthreads();
    float acc = bf[t];
    for (int k = 0; k < HID; k++) acc += s1[k] * Wf[k * HID + t];
    s2[t] = acc;
    __syncthreads();
    float a2 = 0.f;
    for (int k = 0; k < HID; k++) a2 += s2[k] * W2[(HID + k) * HID + t];
    g_gW[g * HID + t] = a2;
}

// ---------------- final projection + scalar aggregation ----------------
__global__ void k_z(const float* __restrict__ H, const float* __restrict__ W3) {
    int node = blockIdx.x * 8 + (threadIdx.x >> 5);
    int lane = threadIdx.x & 31;
    float4 h = ((const float4*)H)[node * 32 + lane];
    float4 w = ((const float4*)W3)[lane];
    float d = h.x * w.x + h.y * w.y + h.z * w.z + h.w * w.w;
    #pragma unroll
    for (int o = 16; o; o >>= 1) d += __shfl_xor_sync(0xffffffffu, d, o);
    if (lane == 0) g_z[node] = d;
}

__global__ void k_logit(const float* __restrict__ b3) {
    int node = blockIdx.x * 8 + (threadIdx.x >> 5);
    int lane = threadIdx.x & 31;
    int jb = g_off[node], je = jb + g_deg[node];
    float part = 0.f;
    for (int j = jb + lane; j < je; j += 32)
        part += g_csrnrm[j] * g_z[g_csrsrc[j]];
    #pragma unroll
    for (int o = 16; o; o >>= 1) part += __shfl_xor_sync(0xffffffffu, part, o);
    if (lane == 0) {
        float dv = g_dinv[node];
        g_logit[node] = part + dv * dv * g_z[node] + b3[0];
    }
}

// ---------------- per-graph top-K threshold + mask ----------------
__global__ void k_topk(float* __restrict__ out) {
    __shared__ float v[NPER];
    __shared__ float wmax[8];
    __shared__ float sth;
    __shared__ int sidx;
    int g = blockIdx.x, t = threadIdx.x;
    int lane = t & 31, warp = t >> 5;
    for (int i = t; i < NPER; i += 256) v[i] = g_logit[g * NPER + i];
    __syncthreads();
    for (int it = 0; it < TOPK; it++) {
        float m = -CUDART_INF_F;
        for (int i = t; i < NPER; i += 256) m = fmaxf(m, v[i]);
        #pragma unroll
        for (int o = 16; o; o >>= 1) m = fmaxf(m, __shfl_xor_sync(0xffffffffu, m, o));
        if (lane == 0) wmax[warp] = m;
        __syncthreads();
        if (t == 0) {
            float mm = wmax[0];
            #pragma unroll
            for (int w = 1; w < 8; w++) mm = fmaxf(mm, wmax[w]);
            sth = mm;
            sidx = 0x7fffffff;
        }
        __syncthreads();
        float mm = sth;
        for (int i = t; i < NPER; i += 256)
            if (v[i] == mm) atomicMin(&sidx, i);
        __syncthreads();
        if (t == 0) v[sidx] = -CUDART_INF_F;
        __syncthreads();
    }
    float th = sth;
    for (int i = t; i < NPER; i += 256)
        out[g * NPER + i] = (g_logit[g * NPER + i] >= th) ? 1.0f : 0.0f;
}

// ---------------- host launcher ----------------
extern "C" void kernel_launch(void* const* d_in, const int* in_sizes, int n_in,
                              void* d_out, int out_size) {
    const float* x    = (const float*)d_in[0];
    const int*   esrc = (const int*)d_in[1];
    const int*   edst = (const int*)d_in[2];
    const float* W0 = (const float*)d_in[4];
    const float* b0 = (const float*)d_in[5];
    const float* W1 = (const float*)d_in[6];
    const float* b1 = (const float*)d_in[7];
    const float* Wf = (const float*)d_in[8];
    const float* bf = (const float*)d_in[9];
    const float* W2 = (const float*)d_in[10];
    const float* b2 = (const float*)d_in[11];
    const float* W3 = (const float*)d_in[12];
    const float* b3 = (const float*)d_in[13];
    float* out = (float*)d_out;

    float *T0, *T1, *T2;
    cudaGetSymbolAddress((void**)&T0, g_T0);
    cudaGetSymbolAddress((void**)&T1, g_T1);
    cudaGetSymbolAddress((void**)&T2, g_T2);

    const int SM64  = (128 * 68 + 64 * 136) * 4;     // 69632
    const int SM128 = (128 * 132 + 128 * 136) * 4;   // 137216
    cudaFuncSetAttribute(k_mgemm<64, true, false>,  cudaFuncAttributeMaxDynamicSharedMemorySize, SM64);
    cudaFuncSetAttribute(k_mgemm<128, true, false>, cudaFuncAttributeMaxDynamicSharedMemorySize, SM128);
    cudaFuncSetAttribute(k_mgemm<128, true, true>,  cudaFuncAttributeMaxDynamicSharedMemorySize, SM128);

    // --- CSR + norms ---
    k_zero_deg<<<NNODES / 256, 256>>>();
    k_hist<<<NEDGES / 256, 256>>>(edst);
    k_dinv<<<NNODES / 256, 256>>>();
    k_scan1<<<256, 256>>>();
    k_scan2<<<1, 256>>>();
    k_scan3<<<256, 256>>>();
    k_fill<<<NEDGES / 256, 256>>>(esrc, edst);
    k_cvec<<<NNODES / 256, 256>>>();

    // --- conv0: h0 = relu(agg(x) @ W0 + b0) ---
    k_agg64<<<NNODES / 8, 256>>>(x, T2);
    k_mgemm<64, true, false><<<NNODES / 128, 256, SM64>>>(T2, W0, b0, T0);

    // --- global path ---
    k_maxpool1<<<NGRAPH * 8, HID>>>(T0);
    k_maxpool2<<<NGRAPH, HID>>>();
    k_globs<<<NGRAPH, HID>>>(Wf, bf, W2);

    // --- conv1 (applied twice with same weights) ---
    k_agg128<<<NNODES / 8, 256>>>(T0, T1);
    k_mgemm<128, true, false><<<NNODES / 128, 256, SM128>>>(T1, W1, b1, T2);
    k_agg128<<<NNODES / 8, 256>>>(T2, T1);
    k_mgemm<128, true, false><<<NNODES / 128, 256, SM128>>>(T1, W1, b1, T0);

    // --- conv2 on concat: relu(agg(h) @ W2_top + c_n * gW + b2) ---
    k_agg128<<<NNODES / 8, 256>>>(T0, T1);
    k_mgemm<128, true, true><<<NNODES / 128, 256, SM128>>>(T1, W2, b2, T2);

    // --- conv3 (out=1): z = h @ W3, logit = agg(z) + b3 ---
    k_z<<<NNODES / 8, 256>>>(T2, W3);
    k_logit<<<NNODES / 8, 256>>>(b3);

    // --- per-graph top-10 threshold mask ---
    k_topk<<<NGRAPH, 256>>>(out);
}